// round 9
// baseline (speedup 1.0000x reference)
#include <cuda_runtime.h>
#include <math.h>

#define BB   4
#define NN   4096
#define CC   128
#define KK1  16
#define KK2  8
#define TDD  64
#define KDIM 131
#define KPAD 144
#define RWS  512
#define NPTS (BB*NN)

typedef unsigned long long u64;

__device__ __forceinline__ u64 ffma2(u64 a, u64 b, u64 c) {
    u64 d;
    asm("fma.rn.f32x2 %0, %1, %2, %3;" : "=l"(d) : "l"(a), "l"(b), "l"(c));
    return d;
}
__device__ __forceinline__ u64 dup2(float x) {
    u64 d;
    asm("mov.b64 %0, {%1, %1};" : "=l"(d) : "r"(__float_as_int(x)));
    return d;
}
__device__ __forceinline__ void unpack2(u64 v, float& lo, float& hi) {
    int a, b;
    asm("mov.b64 {%0, %1}, %2;" : "=r"(a), "=r"(b) : "l"(v));
    lo = __int_as_float(a); hi = __int_as_float(b);
}

// ---------------- scratch ----------------
__device__ int   g_idx[NPTS*KK1];
// per point rows: [0:64)Pq [64:128)Pk [128:256)PvProj [256:320)Sq [320:384)Sk [384:512)SvProj
__device__ float g_P[(size_t)NPTS*RWS];
__device__ float g_WcT[KPAD*RWS];
__device__ float g_bias[RWS];

// ---------------- prep ----------------
__global__ void prep_kernel(const float* __restrict__ wq, const float* __restrict__ wk,
                            const float* __restrict__ wv, const float* __restrict__ bq,
                            const float* __restrict__ bk, const float* __restrict__ bv,
                            const float* __restrict__ w1) {
    int i = blockIdx.x * blockDim.x + threadIdx.x;
    const int total1 = KPAD * RWS;
    if (i < total1) {
        int k = i >> 9;
        int r = i & 511;
        float val = 0.f;
        if (k < KDIM) {
            if (r < 128) {                       // Pq | Pk
                const float* w = (r < 64) ? wq : wk;
                const float* row = w + (r & 63) * 262;
                val = (k < 3) ? row[k] : row[6 + (k - 3)];
            } else if (r < 256) {                // PvProj = w1 @ Pv
                int o = r - 128;
                float s = 0.f;
                for (int m = 0; m < TDD; ++m) {
                    const float* row = wv + m * 262;
                    float wvk = (k < 3) ? row[k] : row[6 + (k - 3)];
                    s = fmaf(w1[o * TDD + m], wvk, s);
                }
                val = s;
            } else if (r < 384) {                // Sq | Sk
                const float* w = (r < 320) ? wq : wk;
                const float* row = w + (r & 63) * 262;
                val = (k < 3) ? (row[3 + k] - row[k])
                              : (row[134 + (k - 3)] - row[6 + (k - 3)]);
            } else {                             // SvProj = w1 @ Sv
                int o = r - 384;
                float s = 0.f;
                for (int m = 0; m < TDD; ++m) {
                    const float* row = wv + m * 262;
                    float d = (k < 3) ? (row[3 + k] - row[k])
                                      : (row[134 + (k - 3)] - row[6 + (k - 3)]);
                    s = fmaf(w1[o * TDD + m], d, s);
                }
                val = s;
            }
        }
        g_WcT[(k << 9) + r] = val;
        return;
    }
    i -= total1;
    if (i < RWS) {
        float bval = 0.f;
        if (i >= 256 && i < 320) bval = bq[i - 256];
        else if (i >= 320 && i < 384) bval = bk[i - 320];
        else if (i >= 384) {
            int o = i - 384;
            float s = 0.f;
            for (int m = 0; m < TDD; ++m) s = fmaf(w1[o * TDD + m], bv[m], s);
            bval = s;
        }
        g_bias[i] = bval;
    }
}

// ---------------- kNN: warp per 4 queries, distributed sorted top-17 lists --------------
// Self is NOT excluded: d(self) = -|q|^2 is the strict minimum -> rank 0 always.
// Emit ranks 1..16. One candidate LDS serves 4 independent query streams.
__global__ __launch_bounds__(256) void knn_kernel(const float* __restrict__ xyz) {
    extern __shared__ float4 sh[];                 // 4096 * 16B = 64KB
    const unsigned FULL = 0xffffffffu;
    const int b = blockIdx.x >> 7;                 // 128 blocks per batch
    const int qbase = (blockIdx.x & 127) * 32;     // 32 queries per block (8 warps x 4)
    const int tid = threadIdx.x;
    const int w = tid >> 5, lane = tid & 31;
    const float* xb = xyz + (size_t)b * 3 * NN;

    for (int i = tid; i < NN; i += 256) {
        float x = xb[i], y = xb[NN + i], z = xb[2 * NN + i];
        float sq = fmaf(z, z, fmaf(y, y, x * x));
        sh[i] = make_float4(x, y, z, sq);
    }
    __syncthreads();

    const int q0i = qbase + 4 * w;
    const float4 q0 = sh[q0i + 0];
    const float4 q1 = sh[q0i + 1];
    const float4 q2 = sh[q0i + 2];
    const float4 q3 = sh[q0i + 3];

    // ---- t = 0: evaluate first 32 candidates for all 4 queries ----
    float dl0, dl1, dl2, dl3;
    int   il0 = lane, il1 = lane, il2 = lane, il3 = lane;
    {
        float4 c = sh[lane];
        dl0 = fmaf(-2.0f, fmaf(q0.z, c.z, fmaf(q0.y, c.y, q0.x * c.x)), c.w);
        dl1 = fmaf(-2.0f, fmaf(q1.z, c.z, fmaf(q1.y, c.y, q1.x * c.x)), c.w);
        dl2 = fmaf(-2.0f, fmaf(q2.z, c.z, fmaf(q2.y, c.y, q2.x * c.x)), c.w);
        dl3 = fmaf(-2.0f, fmaf(q3.z, c.z, fmaf(q3.y, c.y, q3.x * c.x)), c.w);
    }
    // fused bitonic sort across lanes for 4 lists (asc by dist, idx tie-break)
#pragma unroll
    for (int k = 2; k <= 32; k <<= 1) {
#pragma unroll
        for (int j = k >> 1; j > 0; j >>= 1) {
            bool keepLt = (((lane & k) == 0) == ((lane & j) == 0));
            float od; int oi; bool lt, sw;
            od = __shfl_xor_sync(FULL, dl0, j); oi = __shfl_xor_sync(FULL, il0, j);
            lt = (od < dl0) || (od == dl0 && oi < il0);
            sw = keepLt ? lt : !lt; if (sw) { dl0 = od; il0 = oi; }
            od = __shfl_xor_sync(FULL, dl1, j); oi = __shfl_xor_sync(FULL, il1, j);
            lt = (od < dl1) || (od == dl1 && oi < il1);
            sw = keepLt ? lt : !lt; if (sw) { dl1 = od; il1 = oi; }
            od = __shfl_xor_sync(FULL, dl2, j); oi = __shfl_xor_sync(FULL, il2, j);
            lt = (od < dl2) || (od == dl2 && oi < il2);
            sw = keepLt ? lt : !lt; if (sw) { dl2 = od; il2 = oi; }
            od = __shfl_xor_sync(FULL, dl3, j); oi = __shfl_xor_sync(FULL, il3, j);
            lt = (od < dl3) || (od == dl3 && oi < il3);
            sw = keepLt ? lt : !lt; if (sw) { dl3 = od; il3 = oi; }
        }
    }
    float kth0 = __shfl_sync(FULL, dl0, 16);   // 17th smallest
    float kth1 = __shfl_sync(FULL, dl1, 16);
    float kth2 = __shfl_sync(FULL, dl2, 16);
    float kth3 = __shfl_sync(FULL, dl3, 16);

    auto insert_hits = [&](unsigned mask, float d, int t, float& dl, int& il, float& kth) {
        do {
            const int src = __ffs(mask) - 1;
            mask &= mask - 1;
            const float dc = __shfl_sync(FULL, d, src);
            const int   mc = t * 32 + src;
            const float up_d = __shfl_up_sync(FULL, dl, 1);
            const int   up_i = __shfl_up_sync(FULL, il, 1);
            const bool here = dc < dl;                 // strict: stable tie-break
            const bool prev = (lane > 0) && (dc < up_d);
            dl = here ? (prev ? up_d : dc) : dl;
            il = here ? (prev ? up_i : mc) : il;
        } while (mask);
        kth = __shfl_sync(FULL, dl, 16);
    };

    // ---- main scan: one LDS per candidate serves 4 queries ----
#pragma unroll 2
    for (int t = 1; t < NN / 32; ++t) {
        const float4 c = sh[t * 32 + lane];
        float d0 = fmaf(-2.0f, fmaf(q0.z, c.z, fmaf(q0.y, c.y, q0.x * c.x)), c.w);
        float d1 = fmaf(-2.0f, fmaf(q1.z, c.z, fmaf(q1.y, c.y, q1.x * c.x)), c.w);
        float d2 = fmaf(-2.0f, fmaf(q2.z, c.z, fmaf(q2.y, c.y, q2.x * c.x)), c.w);
        float d3 = fmaf(-2.0f, fmaf(q3.z, c.z, fmaf(q3.y, c.y, q3.x * c.x)), c.w);

        unsigned m0 = __ballot_sync(FULL, d0 < kth0);
        unsigned m1 = __ballot_sync(FULL, d1 < kth1);
        unsigned m2 = __ballot_sync(FULL, d2 < kth2);
        unsigned m3 = __ballot_sync(FULL, d3 < kth3);
        if (m0) insert_hits(m0, d0, t, dl0, il0, kth0);
        if (m1) insert_hits(m1, d1, t, dl1, il1, kth1);
        if (m2) insert_hits(m2, d2, t, dl2, il2, kth2);
        if (m3) insert_hits(m3, d3, t, dl3, il3, kth3);
    }

    // ranks 1..16 (rank 0 == self)
    if (lane >= 1 && lane <= KK1) {
        size_t base = ((size_t)b * NN + q0i) * KK1 + (lane - 1);
        g_idx[base]            = il0;
        g_idx[base + KK1]      = il1;
        g_idx[base + 2 * KK1]  = il2;
        g_idx[base + 3 * KK1]  = il3;
    }
}

// ---------------- SGEMM with packed f32x2 FMA ----------------
__global__ __launch_bounds__(256, 2) void gemm_kernel(const float* __restrict__ xyz,
                                                      const float* __restrict__ feature) {
    __shared__ __align__(16) float As[16][128];
    __shared__ __align__(16) float Bs[16][128];

    const int tid = threadIdx.x;
    const int tr = tid >> 4;
    const int tc = tid & 15;
    const int p0 = blockIdx.x * 128;
    const int b  = p0 >> 12;
    const int nl = p0 & (NN - 1);
    const int rowbase = blockIdx.y * 128;

    const int la_k = tid >> 4;
    const int la_r = (tid & 15) * 8;
    const int lb_k = tid >> 4;
    const int lb_j = (tid & 15) * 8;

    u64 acc[8][4];
#pragma unroll
    for (int i = 0; i < 8; ++i)
#pragma unroll
        for (int j = 0; j < 4; ++j) acc[i][j] = 0ull;

    float4 pa0, pa1, pb0, pb1;
    {
        const float* srcA = g_WcT + la_k * RWS + rowbase + la_r;
        pa0 = *(const float4*)srcA; pa1 = *(const float4*)(srcA + 4);
        int kg = lb_k;
        const float* row = (kg < 3) ? (xyz + ((size_t)b * 3 + kg) * NN)
                                    : (feature + ((size_t)b * CC + (kg - 3)) * NN);
        pb0 = *(const float4*)(row + nl + lb_j);
        pb1 = *(const float4*)(row + nl + lb_j + 4);
    }

    for (int kt = 0; kt < KPAD / 16; ++kt) {
        *(float4*)&As[la_k][la_r]     = pa0;
        *(float4*)&As[la_k][la_r + 4] = pa1;
        *(float4*)&Bs[lb_k][lb_j]     = pb0;
        *(float4*)&Bs[lb_k][lb_j + 4] = pb1;
        __syncthreads();
        if (kt + 1 < KPAD / 16) {
            const float* srcA = g_WcT + ((kt + 1) * 16 + la_k) * RWS + rowbase + la_r;
            pa0 = *(const float4*)srcA; pa1 = *(const float4*)(srcA + 4);
            int kg = (kt + 1) * 16 + lb_k;
            if (kg < KDIM) {
                const float* row = (kg < 3) ? (xyz + ((size_t)b * 3 + kg) * NN)
                                            : (feature + ((size_t)b * CC + (kg - 3)) * NN);
                pb0 = *(const float4*)(row + nl + lb_j);
                pb1 = *(const float4*)(row + nl + lb_j + 4);
            } else {
                pb0 = make_float4(0.f, 0.f, 0.f, 0.f);
                pb1 = pb0;
            }
        }
#pragma unroll
        for (int k = 0; k < 16; ++k) {
            float4 a0 = *(const float4*)&As[k][tr * 8];
            float4 a1 = *(const float4*)&As[k][tr * 8 + 4];
            ulonglong2 b0 = *(const ulonglong2*)&Bs[k][tc * 8];
            ulonglong2 b1 = *(const ulonglong2*)&Bs[k][tc * 8 + 4];
            u64 bp[4] = {b0.x, b0.y, b1.x, b1.y};
            float ar[8] = {a0.x, a0.y, a0.z, a0.w, a1.x, a1.y, a1.z, a1.w};
#pragma unroll
            for (int i = 0; i < 8; ++i) {
                u64 a2 = dup2(ar[i]);
#pragma unroll
                for (int j = 0; j < 4; ++j)
                    acc[i][j] = ffma2(a2, bp[j], acc[i][j]);
            }
        }
        __syncthreads();
    }

    const int gr = rowbase + tr * 8;
    float bias[8];
#pragma unroll
    for (int i = 0; i < 8; ++i) bias[i] = g_bias[gr + i];
    float r_[8][8];
#pragma unroll
    for (int i = 0; i < 8; ++i)
#pragma unroll
        for (int j = 0; j < 4; ++j)
            unpack2(acc[i][j], r_[i][2 * j], r_[i][2 * j + 1]);
#pragma unroll
    for (int j = 0; j < 8; ++j) {
        int p = p0 + tc * 8 + j;
        float* dst = g_P + (size_t)p * RWS + gr;
        float4 v0 = make_float4(r_[0][j] + bias[0], r_[1][j] + bias[1],
                                r_[2][j] + bias[2], r_[3][j] + bias[3]);
        float4 v1 = make_float4(r_[4][j] + bias[4], r_[5][j] + bias[5],
                                r_[6][j] + bias[6], r_[7][j] + bias[7]);
        *(float4*)dst       = v0;
        *(float4*)(dst + 4) = v1;
    }
}

// ---------------- attention ----------------
#define WARP_FLOATS 1632
#define SM_RES      (8*WARP_FLOATS)
#define SM_ATTN_TOT (SM_RES + 8*132)

__global__ __launch_bounds__(256, 3) void attn_kernel(const float* __restrict__ feature,
                                                      const float* __restrict__ b1,
                                                      float* __restrict__ out) {
    extern __shared__ __align__(16) float sm[];
    const int tid = threadIdx.x;
    const int w = tid >> 5, l = tid & 31;
    float* qw   = sm + w * WARP_FLOATS;
    float* kw   = qw + 8 * 68;
    float* resT = sm + SM_RES;

    const int gp = blockIdx.x * 8 + w;
    const int b  = gp >> 12;
    const int* ip = g_idx + (size_t)gp * KK1;
    const float* Pbase = g_P + ((size_t)(b << 12)) * RWS;
    const float* Sp    = g_P + (size_t)gp * RWS + 256;

    int c[16];
    {
        int4 t0 = ((const int4*)ip)[0]; int4 t1 = ((const int4*)ip)[1];
        int4 t2 = ((const int4*)ip)[2]; int4 t3 = ((const int4*)ip)[3];
        c[0]=t0.x; c[1]=t0.y; c[2]=t0.z; c[3]=t0.w;
        c[4]=t1.x; c[5]=t1.y; c[6]=t1.z; c[7]=t1.w;
        c[8]=t2.x; c[9]=t2.y; c[10]=t2.z; c[11]=t2.w;
        c[12]=t3.x; c[13]=t3.y; c[14]=t3.z; c[15]=t3.w;
    }

    // ---- gather q = Pq[c] + Sq ----
    {
        int a = l >> 2, qt = l & 3;
        const float4* src = (const float4*)(Pbase + (size_t)c[a] * RWS) + qt * 4;
        const float4* s4  = (const float4*)Sp + qt * 4;
        float4* dst = (float4*)(qw + a * 68 + qt * 16);
#pragma unroll
        for (int f = 0; f < 4; ++f) {
            float4 p = src[f], s = s4[f];
            dst[f] = make_float4(p.x + s.x, p.y + s.y, p.z + s.z, p.w + s.w);
        }
    }
    // ---- gather k = Pk[c] + Sk ----
    {
        int j = l >> 1, h = l & 1;
        const float4* src = (const float4*)(Pbase + (size_t)c[j] * RWS + 64 + h * 32);
        const float4* s4  = (const float4*)(Sp + 64 + h * 32);
        float4* dst = (float4*)(kw + j * 68 + h * 32);
#pragma unroll
        for (int f = 0; f < 8; ++f) {
            float4 p = src[f], s = s4[f];
            dst[f] = make_float4(p.x + s.x, p.y + s.y, p.z + s.z, p.w + s.w);
        }
    }
    __syncwarp();

    // ---- logits with packed f32x2 ----
    const int nq = l & 7, jg = l >> 3;
    u64 acc2[4] = {0ull, 0ull, 0ull, 0ull};
    const ulonglong2* qrow = (const ulonglong2*)(qw + nq * 68);
#pragma unroll
    for (int dc = 0; dc < 4; ++dc) {
        ulonglong2 qa = qrow[dc * 4 + 0], qb = qrow[dc * 4 + 1];
        ulonglong2 qc = qrow[dc * 4 + 2], qd = qrow[dc * 4 + 3];
#pragma unroll
        for (int j4 = 0; j4 < 4; ++j4) {
            const ulonglong2* kr = (const ulonglong2*)(kw + (j4 * 4 + jg) * 68);
            ulonglong2 ka = kr[dc * 4 + 0], kb = kr[dc * 4 + 1];
            ulonglong2 kc = kr[dc * 4 + 2], kd = kr[dc * 4 + 3];
            u64 s = acc2[j4];
            s = ffma2(qa.x, ka.x, s); s = ffma2(qa.y, ka.y, s);
            s = ffma2(qb.x, kb.x, s); s = ffma2(qb.y, kb.y, s);
            s = ffma2(qc.x, kc.x, s); s = ffma2(qc.y, kc.y, s);
            s = ffma2(qd.x, kd.x, s); s = ffma2(qd.y, kd.y, s);
            acc2[j4] = s;
        }
    }
    float acc[4];
#pragma unroll
    for (int j4 = 0; j4 < 4; ++j4) {
        float lo, hi; unpack2(acc2[j4], lo, hi);
        acc[j4] = lo + hi;
    }

    // ---- softmax over j per query row nq ----
    float mx = fmaxf(fmaxf(acc[0], acc[1]), fmaxf(acc[2], acc[3]));
    mx = fmaxf(mx, __shfl_xor_sync(0xffffffffu, mx, 8));
    mx = fmaxf(mx, __shfl_xor_sync(0xffffffffu, mx, 16));
    float e[4], ssum = 0.f;
#pragma unroll
    for (int j4 = 0; j4 < 4; ++j4) { e[j4] = __expf(acc[j4] - mx); ssum += e[j4]; }
    ssum += __shfl_xor_sync(0xffffffffu, ssum, 8);
    ssum += __shfl_xor_sync(0xffffffffu, ssum, 16);
    float inv = 1.0f / ssum;
    float wj[4];
#pragma unroll
    for (int j4 = 0; j4 < 4; ++j4) wj[j4] = e[j4] * inv;

    // ---- colsum over the 8 queries ----
#pragma unroll
    for (int off = 1; off < 8; off <<= 1)
#pragma unroll
        for (int j4 = 0; j4 < 4; ++j4)
            wj[j4] += __shfl_xor_sync(0xffffffffu, wj[j4], off);

    // ---- res128 = sum_j w[j]*PvProj[c_j] + wsum*SvProj (packed) ----
    u64 av0 = 0ull, av1 = 0ull;
#pragma unroll
    for (int j = 0; j < 16; ++j) {
        float wjv = __shfl_sync(0xffffffffu, wj[j >> 2], (j & 3) * 8);
        u64 w2 = dup2(wjv);
        ulonglong2 vv = *(const ulonglong2*)(Pbase + (size_t)c[j] * RWS + 128 + 4 * l);
        av0 = ffma2(w2, vv.x, av0);
        av1 = ffma2(w2, vv.y, av1);
    }
    float wsum = wj[0] + wj[1] + wj[2] + wj[3];
    wsum += __shfl_xor_sync(0xffffffffu, wsum, 8);
    wsum += __shfl_xor_sync(0xffffffffu, wsum, 16);
    {
        u64 w2 = dup2(wsum);
        ulonglong2 sv = *(const ulonglong2*)(Sp + 128 + 4 * l);
        av0 = ffma2(w2, sv.x, av0);
        av1 = ffma2(w2, sv.y, av1);
    }
    {
        float4 r;
        unpack2(av0, r.x, r.y);
        unpack2(av1, r.z, r.w);
        *(float4*)(resT + w * 132 + 4 * l) = r;
    }
    __syncthreads();

    // ---- out = res + b1 + feature ----
    const int o  = tid >> 1;
    const int pg = (tid & 1) * 4;
    const int gp0 = blockIdx.x * 8;
    const int bb = gp0 >> 12, nl = gp0 & (NN - 1);
    size_t base = ((size_t)bb * CC + o) * NN + nl + pg;
    float bo = b1[o];
    float4 fv = *(const float4*)(feature + base);
    float4 ov;
    ov.x = resT[(pg + 0) * 132 + o] + bo + fv.x;
    ov.y = resT[(pg + 1) * 132 + o] + bo + fv.y;
    ov.z = resT[(pg + 2) * 132 + o] + bo + fv.z;
    ov.w = resT[(pg + 3) * 132 + o] + bo + fv.w;
    *(float4*)(out + base) = ov;
}

// ---------------- launch: fork(knn || prep->gemm) -> join -> attn ----------------
extern "C" void kernel_launch(void* const* d_in, const int* in_sizes, int n_in,
                              void* d_out, int out_size) {
    const float* feature = (const float*)d_in[0];
    const float* xyz     = (const float*)d_in[1];
    const float* wq      = (const float*)d_in[2];
    const float* bq      = (const float*)d_in[3];
    const float* wk      = (const float*)d_in[4];
    const float* bk      = (const float*)d_in[5];
    const float* wv      = (const float*)d_in[6];
    const float* bv      = (const float*)d_in[7];
    const float* w1      = (const float*)d_in[8];
    const float* b1      = (const float*)d_in[9];
    float* out = (float*)d_out;

    static cudaStream_t s_aux = []{
        cudaStream_t s; cudaStreamCreateWithFlags(&s, cudaStreamNonBlocking); return s; }();
    static cudaEvent_t ev_fork = []{
        cudaEvent_t e; cudaEventCreateWithFlags(&e, cudaEventDisableTiming); return e; }();
    static cudaEvent_t ev_join = []{
        cudaEvent_t e; cudaEventCreateWithFlags(&e, cudaEventDisableTiming); return e; }();
    static bool attr_done = []{
        cudaFuncSetAttribute(knn_kernel,  cudaFuncAttributeMaxDynamicSharedMemorySize, NN * 16);
        cudaFuncSetAttribute(attn_kernel, cudaFuncAttributeMaxDynamicSharedMemorySize, SM_ATTN_TOT * 4);
        return true; }();
    (void)attr_done;

    const int knn_smem  = NN * 16;
    const int attn_smem = SM_ATTN_TOT * 4;

    cudaEventRecord(ev_fork, 0);
    cudaStreamWaitEvent(s_aux, ev_fork, 0);

    {
        int total = KPAD * RWS + RWS;
        prep_kernel<<<(total + 255) / 256, 256, 0, s_aux>>>(wq, wk, wv, bq, bk, bv, w1);
    }
    gemm_kernel<<<dim3(NPTS / 128, RWS / 128), 256, 0, s_aux>>>(xyz, feature);

    knn_kernel<<<BB * 128, 256, knn_smem>>>(xyz);

    cudaEventRecord(ev_join, s_aux);
    cudaStreamWaitEvent(0, ev_join, 0);

    attn_kernel<<<NPTS / 8, 256, attn_smem>>>(feature, b1, out);
}